// round 16
// baseline (speedup 1.0000x reference)
#include <cuda_runtime.h>
#include <cuda_bf16.h>
#include <math.h>
#include <stdint.h>

#define BB 2
#define TT 1024
#define DD 1024
#define HH 16
#define DHH 64
#define KVL 2048
#define MQ (BB*TT)
#define MKV (BB*KVL)
#define KCAT (2*DD+3)

typedef __nv_bfloat16 bf16;
typedef __nv_bfloat162 bf162;

// ---------------- scratch (static device memory; no allocations) -------------
__device__ bf16  g_qin[MQ*DD];
__device__ bf16  g_kvin[MKV*DD];
__device__ bf16  g_targetbf[MQ*DD];
__device__ bf16  g_q[MQ*DD];
__device__ bf16  g_kv[MKV*2*DD];
__device__ bf16  g_ctx[MQ*DD];
__device__ float g_attn[MQ*DD];
__device__ bf16  g_attnbf[MQ*DD];
__device__ bf16  g_w1pad[DD*2048];
__device__ bf16  g_ipw[3*DD*DD];
__device__ bf16  g_opw[DD*DD];
__device__ float g_gacc[MQ];
__device__ float g_maskf[BB*KVL];

__device__ __forceinline__ float neg_inf() { return __int_as_float(0xff800000); }

__device__ __forceinline__ float gelu_exact(float x) {
    return 0.5f * x * (1.0f + erff(x * 0.70710678118654752f));
}

__device__ __forceinline__ uint32_t packbf(float a, float b) {
    bf162 t = __floats2bfloat162_rn(a, b);
    return *(uint32_t*)&t;
}

__device__ __forceinline__ void mma_bf16(float* c, const uint32_t* a, const uint32_t* b) {
    asm volatile(
        "mma.sync.aligned.m16n8k16.row.col.f32.bf16.bf16.f32 "
        "{%0,%1,%2,%3}, {%4,%5,%6,%7}, {%8,%9}, {%0,%1,%2,%3};"
        : "+f"(c[0]), "+f"(c[1]), "+f"(c[2]), "+f"(c[3])
        : "r"(a[0]), "r"(a[1]), "r"(a[2]), "r"(a[3]), "r"(b[0]), "r"(b[1]));
}

__device__ __forceinline__ void ldm_x4(uint32_t* r, uint32_t addr) {
    asm volatile("ldmatrix.sync.aligned.m8n8.x4.shared.b16 {%0,%1,%2,%3}, [%4];"
                 : "=r"(r[0]), "=r"(r[1]), "=r"(r[2]), "=r"(r[3]) : "r"(addr));
}

__device__ __forceinline__ void cp16(void* smem_dst, const void* gsrc) {
    uint32_t d = (uint32_t)__cvta_generic_to_shared(smem_dst);
    asm volatile("cp.async.cg.shared.global [%0], [%1], 16;\n" :: "r"(d), "l"(gsrc));
}
__device__ __forceinline__ void cp_commit() { asm volatile("cp.async.commit_group;\n"); }
template<int N> __device__ __forceinline__ void cp_wait() {
    asm volatile("cp.async.wait_group %0;\n" :: "n"(N));
}

// ---------------- unified prep kernel -------------------------------------------
#define PREP_N1 (3*DD*DD/8)
#define PREP_N2 (PREP_N1 + DD*DD/8)
#define PREP_N3 (PREP_N2 + DD*2048/8)
#define PREP_N4 (PREP_N3 + MQ)
#define PREP_N5 (PREP_N4 + BB*KVL)

__global__ void prep_kernel(const float* __restrict__ ipw_f, bf16* __restrict__ ipw,
                            const float* __restrict__ opw_f, bf16* __restrict__ opw,
                            const float* __restrict__ w1,    bf16* __restrict__ w1p,
                            float* __restrict__ gacc,
                            const int* __restrict__ mask, float* __restrict__ maskf) {
    int idx = blockIdx.x * blockDim.x + threadIdx.x;
    if (idx < PREP_N1) {
        int i = idx;
        float4 a = ((const float4*)ipw_f)[i*2];
        float4 b = ((const float4*)ipw_f)[i*2+1];
        ((uint4*)ipw)[i] = make_uint4(packbf(a.x,a.y), packbf(a.z,a.w),
                                      packbf(b.x,b.y), packbf(b.z,b.w));
    } else if (idx < PREP_N2) {
        int i = idx - PREP_N1;
        float4 a = ((const float4*)opw_f)[i*2];
        float4 b = ((const float4*)opw_f)[i*2+1];
        ((uint4*)opw)[i] = make_uint4(packbf(a.x,a.y), packbf(a.z,a.w),
                                      packbf(b.x,b.y), packbf(b.z,b.w));
    } else if (idx < PREP_N3) {
        int i = idx - PREP_N2;
        int n = i >> 8;
        int j8 = (i & 255) * 8;
        const float* src = w1 + (size_t)n * KCAT + j8;
        uint4 pk;
        pk.x = packbf(src[0], src[1]); pk.y = packbf(src[2], src[3]);
        pk.z = packbf(src[4], src[5]); pk.w = packbf(src[6], src[7]);
        *(uint4*)(w1p + (size_t)n * 2048 + j8) = pk;
    } else if (idx < PREP_N4) {
        gacc[idx - PREP_N3] = 0.f;
    } else if (idx < PREP_N5) {
        int i = idx - PREP_N4;
        maskf[i] = (mask[i] != 0) ? 0.f : -1e30f;
    }
}

// ---------------- merged LayerNorm ----------------------------------------------
__global__ void __launch_bounds__(256) ln_both(const float* __restrict__ xq,
                                               const float* __restrict__ xkv,
                                               const float* __restrict__ wq,
                                               const float* __restrict__ bq,
                                               const float* __restrict__ wkv,
                                               const float* __restrict__ bkv,
                                               bf16* __restrict__ outq,
                                               bf16* __restrict__ outkv,
                                               bf16* __restrict__ raw_out) {
    int blk = blockIdx.x;
    int tid = threadIdx.x;
    const float* x; const float* w; const float* b; bf16* out;
    int row; bool raw;
    if (blk < MQ) { row = blk; x = xq; w = wq; b = bq; out = outq; raw = true; }
    else          { row = blk - MQ; x = xkv; w = wkv; b = bkv; out = outkv; raw = false; }

    const float4* xr = (const float4*)(x + (size_t)row * DD);
    float4 v = xr[tid];
    if (raw) {
        ((uint2*)(raw_out + (size_t)row * DD))[tid] =
            make_uint2(packbf(v.x, v.y), packbf(v.z, v.w));
    }
    float s  = v.x + v.y + v.z + v.w;
    float sq = v.x*v.x + v.y*v.y + v.z*v.z + v.w*v.w;
    #pragma unroll
    for (int o = 16; o > 0; o >>= 1) {
        s  += __shfl_xor_sync(0xffffffffu, s, o);
        sq += __shfl_xor_sync(0xffffffffu, sq, o);
    }
    __shared__ float rs[8], rq[8];
    int wid = tid >> 5, lid = tid & 31;
    if (lid == 0) { rs[wid] = s; rq[wid] = sq; }
    __syncthreads();
    s = 0.f; sq = 0.f;
    #pragma unroll
    for (int i = 0; i < 8; i++) { s += rs[i]; sq += rq[i]; }
    float mean = s * (1.0f / DD);
    float var  = sq * (1.0f / DD) - mean * mean;
    float rstd = rsqrtf(var + 1e-5f);
    float4 wv = ((const float4*)w)[tid];
    float4 bv = ((const float4*)b)[tid];
    float o0 = (v.x - mean)*rstd*wv.x + bv.x;
    float o1 = (v.y - mean)*rstd*wv.y + bv.y;
    float o2 = (v.z - mean)*rstd*wv.z + bv.z;
    float o3 = (v.w - mean)*rstd*wv.w + bv.w;
    ((uint2*)(out + (size_t)row * DD))[tid] = make_uint2(packbf(o0, o1), packbf(o2, o3));
}

// ================= shared GEMM machinery ========================================
#define GV2_SMEM (3*32768)

#define GEMM_LOAD_STAGE(ST, KC, GA, GW, KK) do {                                  \
    char* base_ = sm + (ST) * 32768;                                              \
    int k0_ = (KC) * 64;                                                          \
    _Pragma("unroll")                                                             \
    for (int i_ = 0; i_ < 8; i_++) {                                              \
        int f_ = i_ * 256 + tid;                                                  \
        int m_ = f_ >> 10;                                                        \
        int r_ = (f_ & 1023) >> 3;                                                \
        int j_ = f_ & 7;                                                          \
        uint32_t off_ = (uint32_t)(r_ * 128 + ((j_ ^ (r_ & 7)) << 4));            \
        const bf16* src_ = (m_ ? (GW) : (GA)) + (size_t)r_ * (KK) + k0_ + j_ * 8; \
        cp16(base_ + m_ * 16384 + off_, src_);                                    \
    }                                                                             \
    cp_commit();                                                                  \
} while (0)

#define GEMM_MAINLOOP(NK, GA, GW, KK) do {                                        \
    GEMM_LOAD_STAGE(0, 0, GA, GW, KK);                                            \
    GEMM_LOAD_STAGE(1, 1, GA, GW, KK);                                            \
    int st = 0;                                                                   \
    for (int kc = 0; kc < (NK); kc++) {                                           \
        if (kc < (NK) - 1) cp_wait<1>(); else cp_wait<0>();                       \
        __syncthreads();                                                          \
        if (kc + 2 < (NK)) {                                                      \
            int s2 = st + 2; if (s2 >= 3) s2 -= 3;                                \
            GEMM_LOAD_STAGE(s2, kc + 2, GA, GW, KK);                              \
        }                                                                         \
        uint32_t aB = (uint32_t)__cvta_generic_to_shared(sm + st * 32768);        \
        uint32_t wB = aB + 16384;                                                 \
        _Pragma("unroll")                                                         \
        for (int s4 = 0; s4 < 4; s4++) {                                          \
            uint32_t a[2][4];                                                     \
            _Pragma("unroll")                                                     \
            for (int mt = 0; mt < 2; mt++) {                                      \
                int r = wm + mt * 16 + (lane & 15);                               \
                int j = s4 * 2 + (lane >> 4);                                     \
                ldm_x4(a[mt], aB + r * 128 + ((j ^ (r & 7)) << 4));               \
            }                                                                     \
            uint32_t bb[4][4];                                                    \
            _Pragma("unroll")                                                     \
            for (int g = 0; g < 4; g++) {                                         \
                int r = wn + g * 16 + ((lane >> 4) << 3) + (lane & 7);            \
                int j = s4 * 2 + ((lane >> 3) & 1);                               \
                ldm_x4(bb[g], wB + r * 128 + ((j ^ (r & 7)) << 4));               \
            }                                                                     \
            _Pragma("unroll")                                                     \
            for (int mt = 0; mt < 2; mt++)                                        \
                _Pragma("unroll")                                                 \
                for (int nt = 0; nt < 8; nt++)                                    \
                    mma_bf16(acc[mt][nt], a[mt], &bb[nt >> 1][(nt & 1) * 2]);     \
        }                                                                         \
        st++; if (st >= 3) st -= 3;                                               \
    }                                                                             \
} while (0)

// ---------------- merged q+kv projection (640 tiles, bf16 out) ------------------
__global__ void __launch_bounds__(256, 2) gemm_proj(const bf16* __restrict__ QIN,
                                                    const bf16* __restrict__ KVIN,
                                                    const bf16* __restrict__ IPW,
                                                    const float* __restrict__ bias,
                                                    bf16* __restrict__ Qout,
                                                    bf16* __restrict__ KVout) {
    extern __shared__ __align__(128) char sm[];
    int tid  = threadIdx.x;
    int lane = tid & 31;
    int warp = tid >> 5;
    int wm = (warp & 3) * 32;
    int wn = (warp >> 2) * 64;
    int qr = lane >> 2, qc = lane & 3;

    int bx = blockIdx.x;
    const bf16 *gA, *gW;
    const float* bi_base;
    bf16* C;
    int bm, bn, N;
    if (bx < 128) {
        bm = (bx >> 3) * 128; bn = (bx & 7) * 128;
        gA = QIN + (size_t)bm * DD;
        gW = IPW + (size_t)bn * DD;
        bi_base = bias;
        C = Qout; N = DD;
    } else {
        int t = bx - 128;
        bm = (t >> 4) * 128; bn = (t & 15) * 128;
        gA = KVIN + (size_t)bm * DD;
        gW = IPW + (size_t)DD*DD + (size_t)bn * DD;
        bi_base = bias + DD;
        C = KVout; N = 2*DD;
    }

    float acc[2][8][4];
    #pragma unroll
    for (int i = 0; i < 2; i++)
        #pragma unroll
        for (int j = 0; j < 8; j++)
            #pragma unroll
            for (int t = 0; t < 4; t++) acc[i][j][t] = 0.f;

    GEMM_MAINLOOP(16, gA, gW, DD);

    #pragma unroll
    for (int mt = 0; mt < 2; mt++) {
        int row0 = bm + wm + mt * 16 + qr;
        #pragma unroll
        for (int nt = 0; nt < 8; nt++) {
            int col = bn + wn + nt * 8 + qc * 2;
            float2 bi = *(const float2*)(bi_base + col);
            float v0 = acc[mt][nt][0] + bi.x;
            float v1 = acc[mt][nt][1] + bi.y;
            float v2 = acc[mt][nt][2] + bi.x;
            float v3 = acc[mt][nt][3] + bi.y;
            *(uint32_t*)(C + (size_t)row0 * N + col)       = packbf(v0, v1);
            *(uint32_t*)(C + (size_t)(row0 + 8) * N + col) = packbf(v2, v3);
        }
    }
}

// ---------------- out_proj GEMM (dual fp32 + bf16 out) --------------------------
__global__ void __launch_bounds__(256, 2) gemm_out(const bf16* __restrict__ A,
                                                   const bf16* __restrict__ W,
                                                   const float* __restrict__ bias,
                                                   float* __restrict__ Cf,
                                                   bf16* __restrict__ Cb) {
    extern __shared__ __align__(128) char sm[];
    int tid  = threadIdx.x;
    int lane = tid & 31;
    int warp = tid >> 5;
    int wm = (warp & 3) * 32;
    int wn = (warp >> 2) * 64;
    int bm = blockIdx.y * 128, bn = blockIdx.x * 128;
    int qr = lane >> 2, qc = lane & 3;
    const int N = DD;

    const bf16* gA = A + (size_t)bm * DD;
    const bf16* gW = W + (size_t)bn * DD;

    float acc[2][8][4];
    #pragma unroll
    for (int i = 0; i < 2; i++)
        #pragma unroll
        for (int j = 0; j < 8; j++)
            #pragma unroll
            for (int t = 0; t < 4; t++) acc[i][j][t] = 0.f;

    GEMM_MAINLOOP(16, gA, gW, DD);

    #pragma unroll
    for (int mt = 0; mt < 2; mt++) {
        int row0 = bm + wm + mt * 16 + qr;
        #pragma unroll
        for (int nt = 0; nt < 8; nt++) {
            int col = bn + wn + nt * 8 + qc * 2;
            float2 bi = *(const float2*)(bias + col);
            float v0 = acc[mt][nt][0] + bi.x;
            float v1 = acc[mt][nt][1] + bi.y;
            float v2 = acc[mt][nt][2] + bi.x;
            float v3 = acc[mt][nt][3] + bi.y;
            *(float2*)(Cf + (size_t)row0 * N + col)       = make_float2(v0, v1);
            *(float2*)(Cf + (size_t)(row0 + 8) * N + col) = make_float2(v2, v3);
            *(uint32_t*)(Cb + (size_t)row0 * N + col)       = packbf(v0, v1);
            *(uint32_t*)(Cb + (size_t)(row0 + 8) * N + col) = packbf(v2, v3);
        }
    }
}

// ---------------- fused gate GEMM ------------------------------------------------
__global__ void __launch_bounds__(256, 2) gemm_gate(const bf16* __restrict__ A1,
                                                    const bf16* __restrict__ A2,
                                                    const bf16* __restrict__ Wp,
                                                    const float* __restrict__ bias,
                                                    const float* __restrict__ w1raw,
                                                    const float* __restrict__ feat,
                                                    const float* __restrict__ w2,
                                                    float* __restrict__ gacc) {
    extern __shared__ __align__(128) char sm[];
    int tid  = threadIdx.x;
    int lane = tid & 31;
    int warp = tid >> 5;
    int wm = (warp & 3) * 32;
    int wn = (warp >> 2) * 64;
    int bm = blockIdx.y * 128, bn = blockIdx.x * 128;
    int qr = lane >> 2, qc = lane & 3;
    const int nk = 32;

    float acc[2][8][4];
    #pragma unroll
    for (int i = 0; i < 2; i++)
        #pragma unroll
        for (int j = 0; j < 8; j++)
            #pragma unroll
            for (int t = 0; t < 4; t++) acc[i][j][t] = 0.f;

    #define LOAD_STAGE_G(ST, KC) do {                                                \
        char* base_ = sm + (ST) * 32768;                                             \
        const bf16* asrc_ = ((KC) < 16) ? A1 : A2;                                   \
        int ka_ = ((KC) < 16) ? (KC) * 64 : ((KC) - 16) * 64;                        \
        _Pragma("unroll")                                                            \
        for (int i_ = 0; i_ < 8; i_++) {                                             \
            int f_ = i_ * 256 + tid;                                                 \
            int m_ = f_ >> 10;                                                       \
            int r_ = (f_ & 1023) >> 3;                                               \
            int j_ = f_ & 7;                                                         \
            uint32_t off_ = (uint32_t)(r_ * 128 + ((j_ ^ (r_ & 7)) << 4));           \
            const bf16* src_ = m_ ? (Wp + (size_t)(bn + r_) * 2048 + (KC)*64 + j_*8) \
                                  : (asrc_ + (size_t)(bm + r_) * DD + ka_ + j_*8);   \
            cp16(base_ + m_ * 16384 + off_, src_);                                   \
        }                                                                            \
        cp_commit();                                                                 \
    } while (0)

    LOAD_STAGE_G(0, 0);
    LOAD_STAGE_G(1, 1);

    int st = 0;
    for (int kc = 0; kc < nk; kc++) {
        if (kc < nk - 1) cp_wait<1>(); else cp_wait<0>();
        __syncthreads();
        if (kc + 2 < nk) {
            int s2 = st + 2; if (s2 >= 3) s2 -= 3;
            LOAD_STAGE_G(s2, kc + 2);
        }

        uint32_t aB = (uint32_t)__cvta_generic_to_shared(sm + st * 32768);
        uint32_t wB = aB + 16384;

        #pragma unroll
        for (int s4 = 0; s4 < 4; s4++) {
            uint32_t a[2][4];
            #pragma unroll
            for (int mt = 0; mt < 2; mt++) {
                int r = wm + mt * 16 + (lane & 15);
                int j = s4 * 2 + (lane >> 4);
                ldm_x4(a[mt], aB + r * 128 + ((j ^ (r & 7)) << 4));
            }
            uint32_t bb[4][4];
            #pragma unroll
            for (int g = 0; g < 4; g++) {
                int r = wn + g * 16 + ((lane >> 4) << 3) + (lane & 7);
                int j = s4 * 2 + ((lane >> 3) & 1);
                ldm_x4(bb[g], wB + r * 128 + ((j ^ (r & 7)) << 4));
            }
            #pragma unroll
            for (int mt = 0; mt < 2; mt++)
                #pragma unroll
                for (int nt = 0; nt < 8; nt++)
                    mma_bf16(acc[mt][nt], a[mt], &bb[nt >> 1][(nt & 1) * 2]);
        }
        st++; if (st >= 3) st -= 3;
    }
    #undef LOAD_STAGE_G

    #pragma unroll
    for (int mt = 0; mt < 2; mt++) {
        int r0 = bm + wm + mt * 16 + qr;
        int r1 = r0 + 8;
        float f0a = feat[r0*3+0], f0b = feat[r0*3+1], f0c = feat[r0*3+2];
        float f1a = feat[r1*3+0], f1b = feat[r1*3+1], f1c = feat[r1*3+2];
        float p0 = 0.f, p1 = 0.f;
        #pragma unroll
        for (int nt = 0; nt < 8; nt++) {
            int col = bn + wn + nt * 8 + qc * 2;
            float2 bi = *(const float2*)(bias + col);
            const float* wtc0 = w1raw + (size_t)col * KCAT + 2*DD;
            const float* wtc1 = w1raw + (size_t)(col+1) * KCAT + 2*DD;
            float t0a = __ldg(wtc0), t0b = __ldg(wtc0+1), t0c = __ldg(wtc0+2);
            float t1a = __ldg(wtc1), t1b = __ldg(wtc1+1), t1c = __ldg(wtc1+2);
            float w2c0 = w2[col], w2c1 = w2[col+1];
            float v0 = acc[mt][nt][0] + bi.x + f0a*t0a + f0b*t0b + f0c*t0c;
            float v1 = acc[mt][nt][1] + bi.y + f0a*t1a + f0b*t1b + f0c*t1c;
            float v2 = acc[mt][nt][2] + bi.x + f1a*t0a + f1b*t0b + f1c*t0c;
            float v3 = acc[mt][nt][3] + bi.y + f1a*t1a + f1b*t1b + f1c*t1c;
            p0 += gelu_exact(v0)*w2c0 + gelu_exact(v1)*w2c1;
            p1 += gelu_exact(v2)*w2c0 + gelu_exact(v3)*w2c1;
        }
        p0 += __shfl_xor_sync(0xffffffffu, p0, 1);
        p0 += __shfl_xor_sync(0xffffffffu, p0, 2);
        p1 += __shfl_xor_sync(0xffffffffu, p1, 1);
        p1 += __shfl_xor_sync(0xffffffffu, p1, 2);
        if ((lane & 3) == 0) {
            atomicAdd(&gacc[r0], p0);
            atomicAdd(&gacc[r1], p1);
        }
    }
}

// ---------------- bf16 flash attention v8: additive mask + ones-mma row sums ----
__global__ void __launch_bounds__(128, 3) attn_v8(const bf16* __restrict__ Q,
                                                  const bf16* __restrict__ KVb,
                                                  const float* __restrict__ maskf,
                                                  bf16* __restrict__ O) {
    __shared__ uint32_t Ks[2][64][36];
    __shared__ uint32_t Vs[2][64][36];
    __shared__ float ms[2][64];

    int tid  = threadIdx.x;
    int lane = tid & 31;
    int warp = tid >> 5;
    int qr = lane >> 2, qc = lane & 3;
    int m0 = warp * 16;
    int b = blockIdx.z, h = blockIdx.y;
    int t0 = blockIdx.x * 64;
    const int NKT = KVL / 64;

    // stage Q scaled by log2(e)/8 into Ks[0]
    {
        float qs = 0.125f * 1.4426950408889634f;
        bf162 sc = __floats2bfloat162_rn(qs, qs);
        #pragma unroll
        for (int u = 0; u < 4; u++) {
            int chunk = u * 128 + tid;
            int row = chunk >> 3, c = chunk & 7;
            uint4 t = *(const uint4*)(Q + ((size_t)(b*TT + t0 + row))*DD + h*DHH + c*8);
            bf162* p = (bf162*)&t;
            p[0] = __hmul2(p[0], sc); p[1] = __hmul2(p[1], sc);
            p[2] = __hmul2(p[2], sc); p[3] = __hmul2(p[3], sc);
            *(uint4*)&Ks[0][row][c*4] = t;
        }
    }
    __syncthreads();

    uint32_t qf[4][4];
    #pragma unroll
    for (int s4 = 0; s4 < 4; s4++) {
        qf[s4][0] = Ks[0][m0+qr  ][s4*8 + qc    ];
        qf[s4][1] = Ks[0][m0+qr+8][s4*8 + qc    ];
        qf[s4][2] = Ks[0][m0+qr  ][s4*8 + qc + 4];
        qf[s4][3] = Ks[0][m0+qr+8][s4*8 + qc + 4];
    }
    __syncthreads();   // all warps done reading Q before cp.async overwrites Ks[0]

    #define ATTN_LOAD(ST, IT) do {                                                 \
        int kv0_ = (IT) * 64;                                                      \
        _Pragma("unroll")                                                          \
        for (int u_ = 0; u_ < 4; u_++) {                                           \
            int chunk_ = u_ * 128 + tid;                                           \
            int row_ = chunk_ >> 3, c_ = chunk_ & 7;                               \
            const bf16* base_ = KVb + ((size_t)(b*KVL + kv0_ + row_))*(2*DD) + h*DHH; \
            cp16(&Ks[ST][row_][c_*4], base_ + c_*8);                               \
            cp16(&Vs[ST][row_][c_*4], base_ + DD + c_*8);                          \
        }                                                                          \
        if (tid < 16) cp16(&ms[ST][tid*4], maskf + (size_t)b*KVL + kv0_ + tid*4);  \
        cp_commit();                                                               \
    } while (0)

    ATTN_LOAD(0, 0);
    ATTN_LOAD(1, 1);

    float o[8][4];
    #pragma unroll
    for (int nt = 0; nt < 8; nt++)
        #pragma unroll
        for (int t = 0; t < 4; t++) o[nt][t] = 0.f;
    float lacc[4] = {0.f, 0.f, 0.f, 0.f};    // ones-mma row-sum accumulator
    const uint32_t onesb[2] = {0x3F803F80u, 0x3F803F80u};

    for (int it = 0; it < NKT; it++) {
        int st = it & 1;
        if (it < NKT - 1) cp_wait<1>(); else cp_wait<0>();
        __syncthreads();   // stage st ready for all warps

        uint32_t ksbase = (uint32_t)__cvta_generic_to_shared(&Ks[st][0][0]);
        uint32_t vbase  = (uint32_t)__cvta_generic_to_shared(&Vs[st][lane & 15][0]);

        // S = Q @ K^T (already in log2 domain)
        float s[8][4];
        #pragma unroll
        for (int nt = 0; nt < 8; nt++)
            #pragma unroll
            for (int t = 0; t < 4; t++) s[nt][t] = 0.f;
        #pragma unroll
        for (int s4 = 0; s4 < 4; s4++) {
            uint32_t kb[4][4];
            #pragma unroll
            for (int g = 0; g < 4; g++) {
                int r = g * 16 + ((lane >> 4) << 3) + (lane & 7);
                uint32_t addr = ksbase + (uint32_t)(r * 144 + s4 * 32 + (((lane >> 3) & 1) << 4));
                ldm_x4(kb[g], addr);
            }
            #pragma unroll
            for (int nt = 0; nt < 8; nt++)
                mma_bf16(s[nt], qf[s4], &kb[nt >> 1][(nt & 1) * 2]);
        }

        // p = exp2(s + additive_mask); masked lanes -> exp2(-1e30) = 0
        #pragma unroll
        for (int nt = 0; nt < 8; nt++) {
            float2 mv = *(const float2*)&ms[st][nt*8 + 2*qc];
            s[nt][0] = exp2f(s[nt][0] + mv.x);
            s[nt][1] = exp2f(s[nt][1] + mv.y);
            s[nt][2] = exp2f(s[nt][2] + mv.x);
            s[nt][3] = exp2f(s[nt][3] + mv.y);
        }

        // O += P @ V; row sums via ones-mma (P direct from registers)
        #pragma unroll
        for (int s4 = 0; s4 < 4; s4++) {
            uint32_t af[4];
            af[0] = packbf(s[2*s4  ][0], s[2*s4  ][1]);
            af[1] = packbf(s[2*s4  ][2], s[2*s4  ][3]);
            af[2] = packbf(s[2*s4+1][0], s[2*s4+1][1]);
            af[3] = packbf(s[2*s4+1][2], s[2*s4+1][3]);
            mma_bf16(lacc, af, onesb);
            #pragma unroll
            for (int nt = 0; nt < 8; nt++) {
                uint32_t b0, b1;
                uint32_t addr = vbase + (uint32_t)((s4*16*36 + nt*4) * 4);
                asm volatile("ldmatrix.sync.aligned.m8n8.x2.trans.shared.b16 {%0,%1}, [%2];"
                             : "=r"(b0), "=r"(b1) : "r"(addr));
                uint32_t bfr[2] = {b0, b1};
                mma_bf16(o[nt], af, bfr);
            }
        }

        __syncthreads();   // all warps done reading stage st
        if (it + 2 < NKT) ATTN_LOAD(st, it + 2);
    }
    #undef ATTN_LOAD

    // lacc columns are identical (B = ones): lacc[0] = rowsum(qr), lacc[2] = rowsum(qr+8)
    float i0 = 1.f / lacc[0], i1 = 1.f / lacc[2];
    bf16* or0 = O + ((size_t)(b*TT + t0 + m0 + qr))*DD + h*DHH;
    bf16* or1 = or0 + (size_t)8*DD;
    #pragma unroll
    for (int nt = 0; nt < 8; nt++) {
        int c0 = nt*8 + 2*qc;
        *(uint32_t*)(or0 + c0) = packbf(o[nt][0]*i0, o[nt][1]*i0);
        *(uint32_t*)(or1 + c0) = packbf(o[nt][2]*i1, o[nt][3]*i1);
    }
}

// ---------------- fuse + residual + output LN (gate inline) --------------------
__global__ void __launch_bounds__(256) final_kernel(const float* __restrict__ target,
                                                    const float* __restrict__ attn,
                                                    const float* __restrict__ gacc,
                                                    const float* __restrict__ b2,
                                                    const float* __restrict__ w,
                                                    const float* __restrict__ bparm,
                                                    float* __restrict__ out,
                                                    float* __restrict__ gate_out) {
    int row = blockIdx.x;
    int tid = threadIdx.x;
    float g = 1.f / (1.f + __expf(-(gacc[row] + b2[0])));
    float4 t4 = ((const float4*)(target + (size_t)row * DD))[tid];
    float4 a4 = ((const float4*)(attn   + (size_t)row * DD))[tid];
    float4 x;
    x.x = (2.f - g)*t4.x + g*a4.x;
    x.y = (2.f - g)*t4.y + g*a4.y;
    x.z = (2.f - g)*t4.z + g*a4.z;
    x.w = (2.f - g)*t4.w + g*a4.w;
    float s  = x.x + x.y + x.z + x.w;
    float sq = x.x*x.x + x.y*x.y + x.z*x.z + x.w*x.w;
    #pragma unroll
    for (int o = 16; o > 0; o >>= 1) {
        s  += __shfl_xor_sync(0xffffffffu, s, o);
        sq += __shfl_xor_sync(0xffffffffu, sq, o);
    }
    __shared__ float rs[8], rq[8];
    int wid = tid >> 5, lid = tid & 31;
    if (lid == 0) { rs[wid] = s; rq[wid] = sq; }
    __syncthreads();
    s = 0.f; sq = 0.f;
    #pragma unroll
    for (int i = 0; i < 8; i++) { s += rs[i]; sq += rq[i]; }
    float mean = s * (1.0f / DD);
    float var  = sq * (1.0f / DD) - mean * mean;
    float rstd = rsqrtf(var + 1e-5f);
    float4 wv = ((const float4*)w)[tid];
    float4 bv = ((const float4*)bparm)[tid];
    float4 o4;
    o4.x = (x.x - mean)*rstd*wv.x + bv.x;
    o4.y = (x.y - mean)*rstd*wv.y + bv.y;
    o4.z = (x.z - mean)*rstd*wv.z + bv.z;
    o4.w = (x.w - mean)*rstd*wv.w + bv.w;
    ((float4*)(out + (size_t)row * DD))[tid] = o4;
    if (gate_out && tid == 0) gate_out[row] = g;
}

// ---------------- launch --------------------------------------------------------
extern "C" void kernel_launch(void* const* d_in, const int* in_sizes, int n_in,
                              void* d_out, int out_size) {
    const float* target   = (const float*)d_in[0];
    const float* support  = (const float*)d_in[1];
    const float* feat     = (const float*)d_in[2];
    const int*   mask     = (const int*)d_in[3];
    const float* ln_q_w   = (const float*)d_in[4];
    const float* ln_q_b   = (const float*)d_in[5];
    const float* ln_kv_w  = (const float*)d_in[6];
    const float* ln_kv_b  = (const float*)d_in[7];
    const float* out_ln_w = (const float*)d_in[8];
    const float* out_ln_b = (const float*)d_in[9];
    const float* in_proj_w  = (const float*)d_in[10];
    const float* in_proj_b  = (const float*)d_in[11];
    const float* out_proj_w = (const float*)d_in[12];
    const float* out_proj_b = (const float*)d_in[13];
    const float* gate_w1 = (const float*)d_in[14];
    const float* gate_b1 = (const float*)d_in[15];
    const float* gate_w2 = (const float*)d_in[16];
    const float* gate_b2 = (const float*)d_in[17];

    bf16 *qin, *kvin, *tbf, *q, *kv, *ctx, *abf, *w1p, *ipw, *opw;
    float *attn, *gacc, *maskf;
    cudaGetSymbolAddress((void**)&qin,   g_qin);
    cudaGetSymbolAddress((void**)&kvin,  g_kvin);
    cudaGetSymbolAddress((void**)&tbf,   g_targetbf);
    cudaGetSymbolAddress((void**)&q,     g_q);
    cudaGetSymbolAddress((void**)&kv,    g_kv);
    cudaGetSymbolAddress((void**)&ctx,   g_ctx);
    cudaGetSymbolAddress((void**)&attn,  g_attn);
    cudaGetSymbolAddress((void**)&abf,   g_attnbf);
    cudaGetSymbolAddress((void**)&w1p,   g_w1pad);
    cudaGetSymbolAddress((void**)&ipw,   g_ipw);
    cudaGetSymbolAddress((void**)&opw,   g_opw);
    cudaGetSymbolAddress((void**)&gacc,  g_gacc);
    cudaGetSymbolAddress((void**)&maskf, g_maskf);

    cudaFuncSetAttribute(gemm_proj, cudaFuncAttributeMaxDynamicSharedMemorySize, GV2_SMEM);
    cudaFuncSetAttribute(gemm_out,  cudaFuncAttributeMaxDynamicSharedMemorySize, GV2_SMEM);
    cudaFuncSetAttribute(gemm_gate, cudaFuncAttributeMaxDynamicSharedMemorySize, GV2_SMEM);

    // 0. unified prep (+ mask -> additive float)
    prep_kernel<<<(PREP_N5 + 255)/256, 256>>>(in_proj_w, ipw, out_proj_w, opw,
                                              gate_w1, w1p, gacc, mask, maskf);

    // 1. merged layernorms (+ raw bf16 target)
    ln_both<<<MQ + MKV, 256>>>(target, support, ln_q_w, ln_q_b,
                               ln_kv_w, ln_kv_b, qin, kvin, tbf);

    // 2. merged q+kv projection
    gemm_proj<<<640, 256, GV2_SMEM>>>(qin, kvin, ipw, in_proj_b, q, kv);

    // 3. attention v8 (additive mask, ones-mma row sums)
    attn_v8<<<dim3(TT/64, HH, BB), 128>>>(q, kv, maskf, ctx);

    // 4. output projection -> fp32 attn + bf16 attn
    gemm_out<<<dim3(DD/128, MQ/128), 256, GV2_SMEM>>>(ctx, opw, out_proj_b, attn, abf);

    // 5. fused gate MLP -> gacc
    gemm_gate<<<dim3(DD/128, MQ/128), 256, GV2_SMEM>>>(tbf, abf, w1p, gate_b1,
                                                       gate_w1, feat, gate_w2, gacc);

    // 6. fuse + residual + output LN (+ gate output)
    float* gout = nullptr;
    if (out_size >= MQ*DD + MQ) gout = (float*)d_out + (size_t)MQ*DD;
    final_kernel<<<MQ, 256>>>(target, attn, gacc, gate_b2, out_ln_w, out_ln_b,
                              (float*)d_out, gout);
}

// round 17
// speedup vs baseline: 1.5169x; 1.5169x over previous
#include <cuda_runtime.h>
#include <cuda_bf16.h>
#include <math.h>
#include <stdint.h>

#define BB 2
#define TT 1024
#define DD 1024
#define HH 16
#define DHH 64
#define KVL 2048
#define MQ (BB*TT)
#define MKV (BB*KVL)
#define KCAT (2*DD+3)

typedef __nv_bfloat16 bf16;
typedef __nv_bfloat162 bf162;

// ---------------- scratch (static device memory; no allocations) -------------
__device__ bf16  g_qin[MQ*DD];
__device__ bf16  g_kvin[MKV*DD];
__device__ bf16  g_targetbf[MQ*DD];
__device__ bf16  g_q[MQ*DD];
__device__ bf16  g_kv[MKV*2*DD];
__device__ bf16  g_ctx[MQ*DD];
__device__ bf16  g_attnbf[MQ*DD];
__device__ bf16  g_w1pad[DD*2048];
__device__ bf16  g_ipw[3*DD*DD];
__device__ bf16  g_opw[DD*DD];
__device__ float g_gacc[MQ];

__device__ __forceinline__ float neg_inf() { return __int_as_float(0xff800000); }

__device__ __forceinline__ float gelu_exact(float x) {
    return 0.5f * x * (1.0f + erff(x * 0.70710678118654752f));
}

__device__ __forceinline__ uint32_t packbf(float a, float b) {
    bf162 t = __floats2bfloat162_rn(a, b);
    return *(uint32_t*)&t;
}

__device__ __forceinline__ void mma_bf16(float* c, const uint32_t* a, const uint32_t* b) {
    asm volatile(
        "mma.sync.aligned.m16n8k16.row.col.f32.bf16.bf16.f32 "
        "{%0,%1,%2,%3}, {%4,%5,%6,%7}, {%8,%9}, {%0,%1,%2,%3};"
        : "+f"(c[0]), "+f"(c[1]), "+f"(c[2]), "+f"(c[3])
        : "r"(a[0]), "r"(a[1]), "r"(a[2]), "r"(a[3]), "r"(b[0]), "r"(b[1]));
}

__device__ __forceinline__ void ldm_x4(uint32_t* r, uint32_t addr) {
    asm volatile("ldmatrix.sync.aligned.m8n8.x4.shared.b16 {%0,%1,%2,%3}, [%4];"
                 : "=r"(r[0]), "=r"(r[1]), "=r"(r[2]), "=r"(r[3]) : "r"(addr));
}

__device__ __forceinline__ void cp16(void* smem_dst, const void* gsrc) {
    uint32_t d = (uint32_t)__cvta_generic_to_shared(smem_dst);
    asm volatile("cp.async.cg.shared.global [%0], [%1], 16;\n" :: "r"(d), "l"(gsrc));
}
__device__ __forceinline__ void cp_commit() { asm volatile("cp.async.commit_group;\n"); }
template<int N> __device__ __forceinline__ void cp_wait() {
    asm volatile("cp.async.wait_group %0;\n" :: "n"(N));
}

// ---------------- unified prep kernel -------------------------------------------
#define PREP_N1 (3*DD*DD/8)
#define PREP_N2 (PREP_N1 + DD*DD/8)
#define PREP_N3 (PREP_N2 + DD*2048/8)
#define PREP_N4 (PREP_N3 + MQ)

__global__ void prep_kernel(const float* __restrict__ ipw_f, bf16* __restrict__ ipw,
                            const float* __restrict__ opw_f, bf16* __restrict__ opw,
                            const float* __restrict__ w1,    bf16* __restrict__ w1p,
                            float* __restrict__ gacc) {
    int idx = blockIdx.x * blockDim.x + threadIdx.x;
    if (idx < PREP_N1) {
        int i = idx;
        float4 a = ((const float4*)ipw_f)[i*2];
        float4 b = ((const float4*)ipw_f)[i*2+1];
        ((uint4*)ipw)[i] = make_uint4(packbf(a.x,a.y), packbf(a.z,a.w),
                                      packbf(b.x,b.y), packbf(b.z,b.w));
    } else if (idx < PREP_N2) {
        int i = idx - PREP_N1;
        float4 a = ((const float4*)opw_f)[i*2];
        float4 b = ((const float4*)opw_f)[i*2+1];
        ((uint4*)opw)[i] = make_uint4(packbf(a.x,a.y), packbf(a.z,a.w),
                                      packbf(b.x,b.y), packbf(b.z,b.w));
    } else if (idx < PREP_N3) {
        int i = idx - PREP_N2;
        int n = i >> 8;
        int j8 = (i & 255) * 8;
        const float* src = w1 + (size_t)n * KCAT + j8;
        uint4 pk;
        pk.x = packbf(src[0], src[1]); pk.y = packbf(src[2], src[3]);
        pk.z = packbf(src[4], src[5]); pk.w = packbf(src[6], src[7]);
        *(uint4*)(w1p + (size_t)n * 2048 + j8) = pk;
    } else if (idx < PREP_N4) {
        gacc[idx - PREP_N3] = 0.f;
    }
}

// ---------------- merged LayerNorm ----------------------------------------------
__global__ void __launch_bounds__(256) ln_both(const float* __restrict__ xq,
                                               const float* __restrict__ xkv,
                                               const float* __restrict__ wq,
                                               const float* __restrict__ bq,
                                               const float* __restrict__ wkv,
                                               const float* __restrict__ bkv,
                                               bf16* __restrict__ outq,
                                               bf16* __restrict__ outkv,
                                               bf16* __restrict__ raw_out) {
    int blk = blockIdx.x;
    int tid = threadIdx.x;
    const float* x; const float* w; const float* b; bf16* out;
    int row; bool raw;
    if (blk < MQ) { row = blk; x = xq; w = wq; b = bq; out = outq; raw = true; }
    else          { row = blk - MQ; x = xkv; w = wkv; b = bkv; out = outkv; raw = false; }

    const float4* xr = (const float4*)(x + (size_t)row * DD);
    float4 v = xr[tid];
    if (raw) {
        ((uint2*)(raw_out + (size_t)row * DD))[tid] =
            make_uint2(packbf(v.x, v.y), packbf(v.z, v.w));
    }
    float s  = v.x + v.y + v.z + v.w;
    float sq = v.x*v.x + v.y*v.y + v.z*v.z + v.w*v.w;
    #pragma unroll
    for (int o = 16; o > 0; o >>= 1) {
        s  += __shfl_xor_sync(0xffffffffu, s, o);
        sq += __shfl_xor_sync(0xffffffffu, sq, o);
    }
    __shared__ float rs[8], rq[8];
    int wid = tid >> 5, lid = tid & 31;
    if (lid == 0) { rs[wid] = s; rq[wid] = sq; }
    __syncthreads();
    s = 0.f; sq = 0.f;
    #pragma unroll
    for (int i = 0; i < 8; i++) { s += rs[i]; sq += rq[i]; }
    float mean = s * (1.0f / DD);
    float var  = sq * (1.0f / DD) - mean * mean;
    float rstd = rsqrtf(var + 1e-5f);
    float4 wv = ((const float4*)w)[tid];
    float4 bv = ((const float4*)b)[tid];
    float o0 = (v.x - mean)*rstd*wv.x + bv.x;
    float o1 = (v.y - mean)*rstd*wv.y + bv.y;
    float o2 = (v.z - mean)*rstd*wv.z + bv.z;
    float o3 = (v.w - mean)*rstd*wv.w + bv.w;
    ((uint2*)(out + (size_t)row * DD))[tid] = make_uint2(packbf(o0, o1), packbf(o2, o3));
}

// ================= shared GEMM machinery ========================================
#define GV2_SMEM (3*32768)

#define GEMM_LOAD_STAGE(ST, KC, GA, GW, KK) do {                                  \
    char* base_ = sm + (ST) * 32768;                                              \
    int k0_ = (KC) * 64;                                                          \
    _Pragma("unroll")                                                             \
    for (int i_ = 0; i_ < 8; i_++) {                                              \
        int f_ = i_ * 256 + tid;                                                  \
        int m_ = f_ >> 10;                                                        \
        int r_ = (f_ & 1023) >> 3;                                                \
        int j_ = f_ & 7;                                                          \
        uint32_t off_ = (uint32_t)(r_ * 128 + ((j_ ^ (r_ & 7)) << 4));            \
        const bf16* src_ = (m_ ? (GW) : (GA)) + (size_t)r_ * (KK) + k0_ + j_ * 8; \
        cp16(base_ + m_ * 16384 + off_, src_);                                    \
    }                                                                             \
    cp_commit();                                                                  \
} while (0)

#define GEMM_MAINLOOP(NK, GA, GW, KK) do {                                        \
    GEMM_LOAD_STAGE(0, 0, GA, GW, KK);                                            \
    GEMM_LOAD_STAGE(1, 1, GA, GW, KK);                                            \
    int st = 0;                                                                   \
    for (int kc = 0; kc < (NK); kc++) {                                           \
        if (kc < (NK) - 1) cp_wait<1>(); else cp_wait<0>();                       \
        __syncthreads();                                                          \
        if (kc + 2 < (NK)) {                                                      \
            int s2 = st + 2; if (s2 >= 3) s2 -= 3;                                \
            GEMM_LOAD_STAGE(s2, kc + 2, GA, GW, KK);                              \
        }                                                                         \
        uint32_t aB = (uint32_t)__cvta_generic_to_shared(sm + st * 32768);        \
        uint32_t wB = aB + 16384;                                                 \
        _Pragma("unroll")                                                         \
        for (int s4 = 0; s4 < 4; s4++) {                                          \
            uint32_t a[2][4];                                                     \
            _Pragma("unroll")                                                     \
            for (int mt = 0; mt < 2; mt++) {                                      \
                int r = wm + mt * 16 + (lane & 15);                               \
                int j = s4 * 2 + (lane >> 4);                                     \
                ldm_x4(a[mt], aB + r * 128 + ((j ^ (r & 7)) << 4));               \
            }                                                                     \
            uint32_t bb[4][4];                                                    \
            _Pragma("unroll")                                                     \
            for (int g = 0; g < 4; g++) {                                         \
                int r = wn + g * 16 + ((lane >> 4) << 3) + (lane & 7);            \
                int j = s4 * 2 + ((lane >> 3) & 1);                               \
                ldm_x4(bb[g], wB + r * 128 + ((j ^ (r & 7)) << 4));               \
            }                                                                     \
            _Pragma("unroll")                                                     \
            for (int mt = 0; mt < 2; mt++)                                        \
                _Pragma("unroll")                                                 \
                for (int nt = 0; nt < 8; nt++)                                    \
                    mma_bf16(acc[mt][nt], a[mt], &bb[nt >> 1][(nt & 1) * 2]);     \
        }                                                                         \
        st++; if (st >= 3) st -= 3;                                               \
    }                                                                             \
} while (0)

// ---------------- merged q+kv projection (640 tiles, bf16 out) ------------------
__global__ void __launch_bounds__(256, 2) gemm_proj(const bf16* __restrict__ QIN,
                                                    const bf16* __restrict__ KVIN,
                                                    const bf16* __restrict__ IPW,
                                                    const float* __restrict__ bias,
                                                    bf16* __restrict__ Qout,
                                                    bf16* __restrict__ KVout) {
    extern __shared__ __align__(128) char sm[];
    int tid  = threadIdx.x;
    int lane = tid & 31;
    int warp = tid >> 5;
    int wm = (warp & 3) * 32;
    int wn = (warp >> 2) * 64;
    int qr = lane >> 2, qc = lane & 3;

    int bx = blockIdx.x;
    const bf16 *gA, *gW;
    const float* bi_base;
    bf16* C;
    int bm, bn, N;
    if (bx < 128) {
        bm = (bx >> 3) * 128; bn = (bx & 7) * 128;
        gA = QIN + (size_t)bm * DD;
        gW = IPW + (size_t)bn * DD;
        bi_base = bias;
        C = Qout; N = DD;
    } else {
        int t = bx - 128;
        bm = (t >> 4) * 128; bn = (t & 15) * 128;
        gA = KVIN + (size_t)bm * DD;
        gW = IPW + (size_t)DD*DD + (size_t)bn * DD;
        bi_base = bias + DD;
        C = KVout; N = 2*DD;
    }

    float acc[2][8][4];
    #pragma unroll
    for (int i = 0; i < 2; i++)
        #pragma unroll
        for (int j = 0; j < 8; j++)
            #pragma unroll
            for (int t = 0; t < 4; t++) acc[i][j][t] = 0.f;

    GEMM_MAINLOOP(16, gA, gW, DD);

    #pragma unroll
    for (int mt = 0; mt < 2; mt++) {
        int row0 = bm + wm + mt * 16 + qr;
        #pragma unroll
        for (int nt = 0; nt < 8; nt++) {
            int col = bn + wn + nt * 8 + qc * 2;
            float2 bi = *(const float2*)(bi_base + col);
            float v0 = acc[mt][nt][0] + bi.x;
            float v1 = acc[mt][nt][1] + bi.y;
            float v2 = acc[mt][nt][2] + bi.x;
            float v3 = acc[mt][nt][3] + bi.y;
            *(uint32_t*)(C + (size_t)row0 * N + col)       = packbf(v0, v1);
            *(uint32_t*)(C + (size_t)(row0 + 8) * N + col) = packbf(v2, v3);
        }
    }
}

// ---------------- out_proj GEMM (bf16 out only) ---------------------------------
__global__ void __launch_bounds__(256, 2) gemm_out(const bf16* __restrict__ A,
                                                   const bf16* __restrict__ W,
                                                   const float* __restrict__ bias,
                                                   bf16* __restrict__ Cb) {
    extern __shared__ __align__(128) char sm[];
    int tid  = threadIdx.x;
    int lane = tid & 31;
    int warp = tid >> 5;
    int wm = (warp & 3) * 32;
    int wn = (warp >> 2) * 64;
    int bm = blockIdx.y * 128, bn = blockIdx.x * 128;
    int qr = lane >> 2, qc = lane & 3;
    const int N = DD;

    const bf16* gA = A + (size_t)bm * DD;
    const bf16* gW = W + (size_t)bn * DD;

    float acc[2][8][4];
    #pragma unroll
    for (int i = 0; i < 2; i++)
        #pragma unroll
        for (int j = 0; j < 8; j++)
            #pragma unroll
            for (int t = 0; t < 4; t++) acc[i][j][t] = 0.f;

    GEMM_MAINLOOP(16, gA, gW, DD);

    #pragma unroll
    for (int mt = 0; mt < 2; mt++) {
        int row0 = bm + wm + mt * 16 + qr;
        #pragma unroll
        for (int nt = 0; nt < 8; nt++) {
            int col = bn + wn + nt * 8 + qc * 2;
            float2 bi = *(const float2*)(bias + col);
            float v0 = acc[mt][nt][0] + bi.x;
            float v1 = acc[mt][nt][1] + bi.y;
            float v2 = acc[mt][nt][2] + bi.x;
            float v3 = acc[mt][nt][3] + bi.y;
            *(uint32_t*)(Cb + (size_t)row0 * N + col)       = packbf(v0, v1);
            *(uint32_t*)(Cb + (size_t)(row0 + 8) * N + col) = packbf(v2, v3);
        }
    }
}

// ---------------- fused gate GEMM ------------------------------------------------
__global__ void __launch_bounds__(256, 2) gemm_gate(const bf16* __restrict__ A1,
                                                    const bf16* __restrict__ A2,
                                                    const bf16* __restrict__ Wp,
                                                    const float* __restrict__ bias,
                                                    const float* __restrict__ w1raw,
                                                    const float* __restrict__ feat,
                                                    const float* __restrict__ w2,
                                                    float* __restrict__ gacc) {
    extern __shared__ __align__(128) char sm[];
    int tid  = threadIdx.x;
    int lane = tid & 31;
    int warp = tid >> 5;
    int wm = (warp & 3) * 32;
    int wn = (warp >> 2) * 64;
    int bm = blockIdx.y * 128, bn = blockIdx.x * 128;
    int qr = lane >> 2, qc = lane & 3;
    const int nk = 32;

    float acc[2][8][4];
    #pragma unroll
    for (int i = 0; i < 2; i++)
        #pragma unroll
        for (int j = 0; j < 8; j++)
            #pragma unroll
            for (int t = 0; t < 4; t++) acc[i][j][t] = 0.f;

    #define LOAD_STAGE_G(ST, KC) do {                                                \
        char* base_ = sm + (ST) * 32768;                                             \
        const bf16* asrc_ = ((KC) < 16) ? A1 : A2;                                   \
        int ka_ = ((KC) < 16) ? (KC) * 64 : ((KC) - 16) * 64;                        \
        _Pragma("unroll")                                                            \
        for (int i_ = 0; i_ < 8; i_++) {                                             \
            int f_ = i_ * 256 + tid;                                                 \
            int m_ = f_ >> 10;                                                       \
            int r_ = (f_ & 1023) >> 3;                                               \
            int j_ = f_ & 7;                                                         \
            uint32_t off_ = (uint32_t)(r_ * 128 + ((j_ ^ (r_ & 7)) << 4));           \
            const bf16* src_ = m_ ? (Wp + (size_t)(bn + r_) * 2048 + (KC)*64 + j_*8) \
                                  : (asrc_ + (size_t)(bm + r_) * DD + ka_ + j_*8);   \
            cp16(base_ + m_ * 16384 + off_, src_);                                   \
        }                                                                            \
        cp_commit();                                                                 \
    } while (0)

    LOAD_STAGE_G(0, 0);
    LOAD_STAGE_G(1, 1);

    int st = 0;
    for (int kc = 0; kc < nk; kc++) {
        if (kc < nk - 1) cp_wait<1>(); else cp_wait<0>();
        __syncthreads();
        if (kc + 2 < nk) {
            int s2 = st + 2; if (s2 >= 3) s2 -= 3;
            LOAD_STAGE_G(s2, kc + 2);
        }

        uint32_t aB = (uint32_t)__cvta_generic_to_shared(sm + st * 32768);
        uint32_t wB = aB + 16384;

        #pragma unroll
        for (int s4 = 0; s4 < 4; s4++) {
            uint32_t a[2][4];
            #pragma unroll
            for (int mt = 0; mt < 2; mt++) {
                int r = wm + mt * 16 + (lane & 15);
                int j = s4 * 2 + (lane >> 4);
                ldm_x4(a[mt], aB + r * 128 + ((j ^ (r & 7)) << 4));
            }
            uint32_t bb[4][4];
            #pragma unroll
            for (int g = 0; g < 4; g++) {
                int r = wn + g * 16 + ((lane >> 4) << 3) + (lane & 7);
                int j = s4 * 2 + ((lane >> 3) & 1);
                ldm_x4(bb[g], wB + r * 128 + ((j ^ (r & 7)) << 4));
            }
            #pragma unroll
            for (int mt = 0; mt < 2; mt++)
                #pragma unroll
                for (int nt = 0; nt < 8; nt++)
                    mma_bf16(acc[mt][nt], a[mt], &bb[nt >> 1][(nt & 1) * 2]);
        }
        st++; if (st >= 3) st -= 3;
    }
    #undef LOAD_STAGE_G

    #pragma unroll
    for (int mt = 0; mt < 2; mt++) {
        int r0 = bm + wm + mt * 16 + qr;
        int r1 = r0 + 8;
        float f0a = feat[r0*3+0], f0b = feat[r0*3+1], f0c = feat[r0*3+2];
        float f1a = feat[r1*3+0], f1b = feat[r1*3+1], f1c = feat[r1*3+2];
        float p0 = 0.f, p1 = 0.f;
        #pragma unroll
        for (int nt = 0; nt < 8; nt++) {
            int col = bn + wn + nt * 8 + qc * 2;
            float2 bi = *(const float2*)(bias + col);
            const float* wtc0 = w1raw + (size_t)col * KCAT + 2*DD;
            const float* wtc1 = w1raw + (size_t)(col+1) * KCAT + 2*DD;
            float t0a = __ldg(wtc0), t0b = __ldg(wtc0+1), t0c = __ldg(wtc0+2);
            float t1a = __ldg(wtc1), t1b = __ldg(wtc1+1), t1c = __ldg(wtc1+2);
            float w2c0 = w2[col], w2c1 = w2[col+1];
            float v0 = acc[mt][nt][0] + bi.x + f0a*t0a + f0b*t0b + f0c*t0c;
            float v1 = acc[mt][nt][1] + bi.y + f0a*t1a + f0b*t1b + f0c*t1c;
            float v2 = acc[mt][nt][2] + bi.x + f1a*t0a + f1b*t0b + f1c*t0c;
            float v3 = acc[mt][nt][3] + bi.y + f1a*t1a + f1b*t1b + f1c*t1c;
            p0 += gelu_exact(v0)*w2c0 + gelu_exact(v1)*w2c1;
            p1 += gelu_exact(v2)*w2c0 + gelu_exact(v3)*w2c1;
        }
        p0 += __shfl_xor_sync(0xffffffffu, p0, 1);
        p0 += __shfl_xor_sync(0xffffffffu, p0, 2);
        p1 += __shfl_xor_sync(0xffffffffu, p1, 1);
        p1 += __shfl_xor_sync(0xffffffffu, p1, 2);
        if ((lane & 3) == 0) {
            atomicAdd(&gacc[r0], p0);
            atomicAdd(&gacc[r1], p1);
        }
    }
}

// ---------------- bf16 flash attention v7 (round-15 proven) ---------------------
__global__ void __launch_bounds__(128, 3) attn_v7(const bf16* __restrict__ Q,
                                                  const bf16* __restrict__ KVb,
                                                  const int* __restrict__ mask,
                                                  bf16* __restrict__ O) {
    __shared__ uint32_t Ks[2][64][36];
    __shared__ uint32_t Vs[2][64][36];
    __shared__ int ms[2][64];

    int tid  = threadIdx.x;
    int lane = tid & 31;
    int warp = tid >> 5;
    int qr = lane >> 2, qc = lane & 3;
    int m0 = warp * 16;
    int b = blockIdx.z, h = blockIdx.y;
    int t0 = blockIdx.x * 64;
    const int NKT = KVL / 64;

    {
        float qs = 0.125f * 1.4426950408889634f;
        bf162 sc = __floats2bfloat162_rn(qs, qs);
        #pragma unroll
        for (int u = 0; u < 4; u++) {
            int chunk = u * 128 + tid;
            int row = chunk >> 3, c = chunk & 7;
            uint4 t = *(const uint4*)(Q + ((size_t)(b*TT + t0 + row))*DD + h*DHH + c*8);
            bf162* p = (bf162*)&t;
            p[0] = __hmul2(p[0], sc); p[1] = __hmul2(p[1], sc);
            p[2] = __hmul2(p[2], sc); p[3] = __hmul2(p[3], sc);
            *(uint4*)&Ks[0][row][c*4] = t;
        }
    }
    __syncthreads();

    uint32_t qf[4][4];
    #pragma unroll
    for (int s4 = 0; s4 < 4; s4++) {
        qf[s4][0] = Ks[0][m0+qr  ][s4*8 + qc    ];
        qf[s4][1] = Ks[0][m0+qr+8][s4*8 + qc    ];
        qf[s4][2] = Ks[0][m0+qr  ][s4*8 + qc + 4];
        qf[s4][3] = Ks[0][m0+qr+8][s4*8 + qc + 4];
    }
    __syncthreads();

    #define ATTN_LOAD(ST, IT) do {                                                 \
        int kv0_ = (IT) * 64;                                                      \
        _Pragma("unroll")                                                          \
        for (int u_ = 0; u_ < 4; u_++) {                                           \
            int chunk_ = u_ * 128 + tid;                                           \
            int row_ = chunk_ >> 3, c_ = chunk_ & 7;                               \
            const bf16* base_ = KVb + ((size_t)(b*KVL + kv0_ + row_))*(2*DD) + h*DHH; \
            cp16(&Ks[ST][row_][c_*4], base_ + c_*8);                               \
            cp16(&Vs[ST][row_][c_*4], base_ + DD + c_*8);                          \
        }                                                                          \
        if (tid < 16) cp16(&ms[ST][tid*4], mask + (size_t)b*KVL + kv0_ + tid*4);   \
        cp_commit();                                                               \
    } while (0)

    ATTN_LOAD(0, 0);
    ATTN_LOAD(1, 1);

    float o[8][4];
    #pragma unroll
    for (int nt = 0; nt < 8; nt++)
        #pragma unroll
        for (int t = 0; t < 4; t++) o[nt][t] = 0.f;
    float l0 = 0.f, l1 = 0.f;

    for (int it = 0; it < NKT; it++) {
        int st = it & 1;
        if (it < NKT - 1) cp_wait<1>(); else cp_wait<0>();
        __syncthreads();

        uint32_t ksbase = (uint32_t)__cvta_generic_to_shared(&Ks[st][0][0]);
        uint32_t vbase  = (uint32_t)__cvta_generic_to_shared(&Vs[st][lane & 15][0]);

        float s[8][4];
        #pragma unroll
        for (int nt = 0; nt < 8; nt++)
            #pragma unroll
            for (int t = 0; t < 4; t++) s[nt][t] = 0.f;
        #pragma unroll
        for (int s4 = 0; s4 < 4; s4++) {
            uint32_t kb[4][4];
            #pragma unroll
            for (int g = 0; g < 4; g++) {
                int r = g * 16 + ((lane >> 4) << 3) + (lane & 7);
                uint32_t addr = ksbase + (uint32_t)(r * 144 + s4 * 32 + (((lane >> 3) & 1) << 4));
                ldm_x4(kb[g], addr);
            }
            #pragma unroll
            for (int nt = 0; nt < 8; nt++)
                mma_bf16(s[nt], qf[s4], &kb[nt >> 1][(nt & 1) * 2]);
        }

        #pragma unroll
        for (int nt = 0; nt < 8; nt++) {
            int c0 = nt*8 + 2*qc;
            if (ms[st][c0] == 0)     { s[nt][0] = neg_inf(); s[nt][2] = neg_inf(); }
            if (ms[st][c0 + 1] == 0) { s[nt][1] = neg_inf(); s[nt][3] = neg_inf(); }
            s[nt][0] = exp2f(s[nt][0]);
            s[nt][1] = exp2f(s[nt][1]);
            s[nt][2] = exp2f(s[nt][2]);
            s[nt][3] = exp2f(s[nt][3]);
            l0 += s[nt][0] + s[nt][1];
            l1 += s[nt][2] + s[nt][3];
        }

        #pragma unroll
        for (int s4 = 0; s4 < 4; s4++) {
            uint32_t af[4];
            af[0] = packbf(s[2*s4  ][0], s[2*s4  ][1]);
            af[1] = packbf(s[2*s4  ][2], s[2*s4  ][3]);
            af[2] = packbf(s[2*s4+1][0], s[2*s4+1][1]);
            af[3] = packbf(s[2*s4+1][2], s[2*s4+1][3]);
            #pragma unroll
            for (int nt = 0; nt < 8; nt++) {
                uint32_t b0, b1;
                uint32_t addr = vbase + (uint32_t)((s4*16*36 + nt*4) * 4);
                asm volatile("ldmatrix.sync.aligned.m8n8.x2.trans.shared.b16 {%0,%1}, [%2];"
                             : "=r"(b0), "=r"(b1) : "r"(addr));
                uint32_t bfr[2] = {b0, b1};
                mma_bf16(o[nt], af, bfr);
            }
        }

        __syncthreads();
        if (it + 2 < NKT) ATTN_LOAD(st, it + 2);
    }
    #undef ATTN_LOAD

    l0 += __shfl_xor_sync(0xffffffffu, l0, 1);
    l0 += __shfl_xor_sync(0xffffffffu, l0, 2);
    l1 += __shfl_xor_sync(0xffffffffu, l1, 1);
    l1 += __shfl_xor_sync(0xffffffffu, l1, 2);

    float i0 = 1.f / l0, i1 = 1.f / l1;
    bf16* or0 = O + ((size_t)(b*TT + t0 + m0 + qr))*DD + h*DHH;
    bf16* or1 = or0 + (size_t)8*DD;
    #pragma unroll
    for (int nt = 0; nt < 8; nt++) {
        int c0 = nt*8 + 2*qc;
        *(uint32_t*)(or0 + c0) = packbf(o[nt][0]*i0, o[nt][1]*i0);
        *(uint32_t*)(or1 + c0) = packbf(o[nt][2]*i1, o[nt][3]*i1);
    }
}

// ---------------- fuse + residual + output LN (bf16 attn input) ----------------
__global__ void __launch_bounds__(256) final_kernel(const float* __restrict__ target,
                                                    const bf16* __restrict__ attnb,
                                                    const float* __restrict__ gacc,
                                                    const float* __restrict__ b2,
                                                    const float* __restrict__ w,
                                                    const float* __restrict__ bparm,
                                                    float* __restrict__ out,
                                                    float* __restrict__ gate_out) {
    int row = blockIdx.x;
    int tid = threadIdx.x;
    float g = 1.f / (1.f + __expf(-(gacc[row] + b2[0])));
    float4 t4 = ((const float4*)(target + (size_t)row * DD))[tid];
    uint2 ap = ((const uint2*)(attnb + (size_t)row * DD))[tid];
    bf162 a01 = *(bf162*)&ap.x;
    bf162 a23 = *(bf162*)&ap.y;
    float4 a4 = make_float4(__bfloat162float(a01.x), __bfloat162float(a01.y),
                            __bfloat162float(a23.x), __bfloat162float(a23.y));
    float4 x;
    x.x = (2.f - g)*t4.x + g*a4.x;
    x.y = (2.f - g)*t4.y + g*a4.y;
    x.z = (2.f - g)*t4.z + g*a4.z;
    x.w = (2.f - g)*t4.w + g*a4.w;
    float s  = x.x + x.y + x.z + x.w;
    float sq = x.x*x.x + x.y*x.y + x.z*x.z + x.w*x.w;
    #pragma unroll
    for (int o = 16; o > 0; o >>= 1) {
        s  += __shfl_xor_sync(0xffffffffu, s, o);
        sq += __shfl_xor_sync(0xffffffffu, sq, o);
    }
    __shared__ float rs[8], rq[8];
    int wid = tid >> 5, lid = tid & 31;
    if (lid == 0) { rs[wid] = s; rq[wid] = sq; }
    __syncthreads();
    s = 0.f; sq = 0.f;
    #pragma unroll
    for (int i = 0; i < 8; i++) { s += rs[i]; sq += rq[i]; }
    float mean = s * (1.0f / DD);
    float var  = sq * (1.0f / DD) - mean * mean;
    float rstd = rsqrtf(var + 1e-5f);
    float4 wv = ((const float4*)w)[tid];
    float4 bv = ((const float4*)bparm)[tid];
    float4 o4;
    o4.x = (x.x - mean)*rstd*wv.x + bv.x;
    o4.y = (x.y - mean)*rstd*wv.y + bv.y;
    o4.z = (x.z - mean)*rstd*wv.z + bv.z;
    o4.w = (x.w - mean)*rstd*wv.w + bv.w;
    ((float4*)(out + (size_t)row * DD))[tid] = o4;
    if (gate_out && tid == 0) gate_out[row] = g;
}

// ---------------- launch --------------------------------------------------------
extern "C" void kernel_launch(void* const* d_in, const int* in_sizes, int n_in,
                              void* d_out, int out_size) {
    const float* target   = (const float*)d_in[0];
    const float* support  = (const float*)d_in[1];
    const float* feat     = (const float*)d_in[2];
    const int*   mask     = (const int*)d_in[3];
    const float* ln_q_w   = (const float*)d_in[4];
    const float* ln_q_b   = (const float*)d_in[5];
    const float* ln_kv_w  = (const float*)d_in[6];
    const float* ln_kv_b  = (const float*)d_in[7];
    const float* out_ln_w = (const float*)d_in[8];
    const float* out_ln_b = (const float*)d_in[9];
    const float* in_proj_w  = (const float*)d_in[10];
    const float* in_proj_b  = (const float*)d_in[11];
    const float* out_proj_w = (const float*)d_in[12];
    const float* out_proj_b = (const float*)d_in[13];
    const float* gate_w1 = (const float*)d_in[14];
    const float* gate_b1 = (const float*)d_in[15];
    const float* gate_w2 = (const float*)d_in[16];
    const float* gate_b2 = (const float*)d_in[17];

    bf16 *qin, *kvin, *tbf, *q, *kv, *ctx, *abf, *w1p, *ipw, *opw;
    float *gacc;
    cudaGetSymbolAddress((void**)&qin,  g_qin);
    cudaGetSymbolAddress((void**)&kvin, g_kvin);
    cudaGetSymbolAddress((void**)&tbf,  g_targetbf);
    cudaGetSymbolAddress((void**)&q,    g_q);
    cudaGetSymbolAddress((void**)&kv,   g_kv);
    cudaGetSymbolAddress((void**)&ctx,  g_ctx);
    cudaGetSymbolAddress((void**)&abf,  g_attnbf);
    cudaGetSymbolAddress((void**)&w1p,  g_w1pad);
    cudaGetSymbolAddress((void**)&ipw,  g_ipw);
    cudaGetSymbolAddress((void**)&opw,  g_opw);
    cudaGetSymbolAddress((void**)&gacc, g_gacc);

    cudaFuncSetAttribute(gemm_proj, cudaFuncAttributeMaxDynamicSharedMemorySize, GV2_SMEM);
    cudaFuncSetAttribute(gemm_out,  cudaFuncAttributeMaxDynamicSharedMemorySize, GV2_SMEM);
    cudaFuncSetAttribute(gemm_gate, cudaFuncAttributeMaxDynamicSharedMemorySize, GV2_SMEM);

    // 0. unified prep
    prep_kernel<<<(PREP_N4 + 255)/256, 256>>>(in_proj_w, ipw, out_proj_w, opw,
                                              gate_w1, w1p, gacc);

    // 1. merged layernorms (+ raw bf16 target)
    ln_both<<<MQ + MKV, 256>>>(target, support, ln_q_w, ln_q_b,
                               ln_kv_w, ln_kv_b, qin, kvin, tbf);

    // 2. merged q+kv projection
    gemm_proj<<<640, 256, GV2_SMEM>>>(qin, kvin, ipw, in_proj_b, q, kv);

    // 3. attention v7 (round-15 proven)
    attn_v7<<<dim3(TT/64, HH, BB), 128>>>(q, kv, mask, ctx);

    // 4. output projection -> bf16 attn only
    gemm_out<<<dim3(DD/128, MQ/128), 256, GV2_SMEM>>>(ctx, opw, out_proj_b, abf);

    // 5. fused gate MLP -> gacc
    gemm_gate<<<dim3(DD/128, MQ/128), 256, GV2_SMEM>>>(tbf, abf, w1p, gate_b1,
                                                       gate_w1, feat, gate_w2, gacc);

    // 6. fuse + residual + output LN (+ gate output), bf16 attn input
    float* gout = nullptr;
    if (out_size >= MQ*DD + MQ) gout = (float*)d_out + (size_t)MQ*DD;
    final_kernel<<<MQ, 256>>>(target, abf, gacc, gate_b2, out_ln_w, out_ln_b,
                              (float*)d_out, gout);
}